// round 15
// baseline (speedup 1.0000x reference)
#include <cuda_runtime.h>
#include <cstdint>
#include <cstddef>

// out[m] = x[m] @ w[sel[m]]   M=262144, K=64, N=64, E=8, fp32
//
// R14: coalesce the scattered x-gather and out-scatter through per-warp
// smem transpose tiles (pitch 80B = stride-5 in 16B units -> conflict-free),
// double-buffered so the next K-slice's LDG overlaps compute.
// Weight reads stay warp-uniform smem broadcasts; math stays fp32x2 FMA.

#define TOK_M   262144
#define NCTA    152
#define NTHR    256
#define NWARP   8
#define MAXTB   1760          // ceil(262144/152)=1725, padded

#define PITCH       80                        // bytes per tile row (64B + 16B pad)
#define STAGE_ROWS  64
#define STAGE_BYTES (STAGE_ROWS * PITCH)      // 5120 per buffer

#define SMEM_W_BYTES   (8 * 64 * 64 * 4)                 // 131072
#define SMEM_STAGE_OFF SMEM_W_BYTES
#define SMEM_STAGE_BYT (NWARP * 2 * STAGE_BYTES)         // 81920
#define SMEM_IDX_OFF   (SMEM_STAGE_OFF + SMEM_STAGE_BYT) // u16[MAXTB]
#define SMEM_SEL_OFF   (SMEM_IDX_OFF + MAXTB * 2)        // u8[MAXTB]
#define SMEM_META_OFF  ((SMEM_SEL_OFF + MAXTB + 15) & ~15)
#define SMEM_TOTAL     (SMEM_META_OFF + 160)

static __device__ __forceinline__ uint32_t s2u(const void* p) {
    uint32_t a;
    asm("{ .reg .u64 t; cvta.to.shared.u64 t, %1; cvt.u32.u64 %0, t; }"
        : "=r"(a) : "l"(p));
    return a;
}

__global__ void __launch_bounds__(NTHR, 1)
cvmm_kernel(const float* __restrict__ x, const int* __restrict__ sel,
            const float* __restrict__ w, float* __restrict__ out)
{
    extern __shared__ char smem[];
    float*          w_s      = (float*)smem;
    unsigned short* idx      = (unsigned short*)(smem + SMEM_IDX_OFF);
    unsigned char*  sel_s    = (unsigned char*)(smem + SMEM_SEL_OFF);
    int*            counts   = (int*)(smem + SMEM_META_OFF);
    int*            offs     = counts + 8;
    int*            cursor   = offs + 8;
    int*            chunkoff = cursor + 8;   // 9 entries

    const int tid = threadIdx.x;
    const int bid = blockIdx.x;
    const int t0 = (int)(((long long)bid       * TOK_M) / NCTA);
    const int t1 = (int)(((long long)(bid + 1) * TOK_M) / NCTA);
    const int TB = t1 - t0;

    if (tid < 8) counts[tid] = 0;

    // ---- stage all expert weights into smem (coalesced float4 copy) ----
    {
        const float4* wg = (const float4*)w;
        float4*       ws = (float4*)w_s;
        #pragma unroll
        for (int i = 0; i < (SMEM_W_BYTES / 16) / NTHR; i++)
            ws[tid + i * NTHR] = wg[tid + i * NTHR];
    }
    __syncthreads();

    // ---- histogram over experts; stage sel in smem ----
    for (int i = tid; i < TB; i += NTHR) {
        int e = sel[t0 + i] & 7;
        sel_s[i] = (unsigned char)e;
        atomicAdd(&counts[e], 1);
    }
    __syncthreads();

    // ---- exclusive scan + 64-token chunk offsets (serial, 8 entries) ----
    if (tid == 0) {
        int acc = 0, cacc = 0;
        #pragma unroll
        for (int e = 0; e < 8; e++) {
            offs[e]     = acc;
            cursor[e]   = acc;
            chunkoff[e] = cacc;
            int c = counts[e];
            acc  += c;
            cacc += (c + 63) >> 6;
        }
        chunkoff[8] = cacc;
    }
    __syncthreads();

    // ---- scatter token local indices into per-expert lists ----
    for (int i = tid; i < TB; i += NTHR) {
        int e = sel_s[i];
        int p = atomicAdd(&cursor[e], 1);
        idx[p] = (unsigned short)i;
    }
    __syncthreads();

    // ---- phase 2: 64-token single-expert chunks, 2 tokens per lane ----
    const int nchunks = chunkoff[8];
    const int warp = tid >> 5, lane = tid & 31;
    const uint32_t wsb  = s2u(w_s);
    const uint32_t stg0 = s2u(smem + SMEM_STAGE_OFF) + (uint32_t)warp * 2 * STAGE_BYTES;
    const int grow = lane & 7;     // gather/scatter row within group of 8
    const int gcol = lane >> 3;    // 0..3 : 16-byte column

    for (int c = warp; c < nchunks; c += NWARP) {
        // expert owning chunk c (monotone chunkoff; highest match wins)
        int e = 0;
        #pragma unroll
        for (int q = 1; q < 8; q++)
            if (chunkoff[q] <= c) e = q;

        const int cc   = c - chunkoff[e];
        const int base = offs[e] + cc * 64;
        const int nrem = counts[e] - cc * 64;          // 1..64

        // token ids for this lane's gather/scatter rows (clamped)
        int tokg[8];
        #pragma unroll
        for (int i = 0; i < 8; i++) {
            int r  = i * 8 + grow;
            int li = base + (r < nrem ? r : nrem - 1);
            tokg[i] = t0 + (int)idx[li];
        }

        unsigned long long acc0[32], acc1[32];
        #pragma unroll
        for (int j = 0; j < 32; j++) { acc0[j] = 0ull; acc1[j] = 0ull; }

        const uint32_t webase = wsb + (uint32_t)e * 16384u;

        // prefetch K-slice 0 (coalesced: 8 rows per warp instruction)
        float4 g[8];
        #pragma unroll
        for (int i = 0; i < 8; i++)
            g[i] = ((const float4*)x)[(size_t)tokg[i] * 16 + gcol];

        #pragma unroll
        for (int kb = 0; kb < 4; kb++) {
            const uint32_t bufb = stg0 + (uint32_t)(kb & 1) * STAGE_BYTES;

            // stage gathered slice into transpose tile
            #pragma unroll
            for (int i = 0; i < 8; i++) {
                uint32_t a = bufb + (uint32_t)(i * 8 + grow) * PITCH
                                  + (uint32_t)gcol * 16u;
                asm volatile("st.shared.v4.b32 [%0], {%1,%2,%3,%4};"
                             :: "r"(a), "f"(g[i].x), "f"(g[i].y),
                                "f"(g[i].z), "f"(g[i].w));
            }
            // prefetch next K-slice while this one computes
            if (kb < 3) {
                #pragma unroll
                for (int i = 0; i < 8; i++)
                    g[i] = ((const float4*)x)[(size_t)tokg[i] * 16
                                              + (kb + 1) * 4 + gcol];
            }
            __syncwarp();

            // read my 2 tokens' 16-float K-slices (conflict-free: stride 5)
            float xa[16], xb[16];
            #pragma unroll
            for (int j = 0; j < 4; j++) {
                uint32_t a0 = bufb + (uint32_t)lane * PITCH + j * 16u;
                uint32_t a1 = bufb + (uint32_t)(lane + 32) * PITCH + j * 16u;
                asm volatile("ld.shared.v4.b32 {%0,%1,%2,%3}, [%4];"
                             : "=f"(xa[4*j]), "=f"(xa[4*j+1]),
                               "=f"(xa[4*j+2]), "=f"(xa[4*j+3]) : "r"(a0));
                asm volatile("ld.shared.v4.b32 {%0,%1,%2,%3}, [%4];"
                             : "=f"(xb[4*j]), "=f"(xb[4*j+1]),
                               "=f"(xb[4*j+2]), "=f"(xb[4*j+3]) : "r"(a1));
            }

            const uint32_t kbase = webase + (uint32_t)kb * 4096u;
            #pragma unroll
            for (int k2 = 0; k2 < 16; k2++) {
                unsigned long long xa2, xb2;
                asm("mov.b64 %0, {%1, %1};" : "=l"(xa2) : "f"(xa[k2]));
                asm("mov.b64 %0, {%1, %1};" : "=l"(xb2) : "f"(xb[k2]));
                const uint32_t a = kbase + (uint32_t)k2 * 256u;
                #pragma unroll
                for (int j = 0; j < 16; j++) {
                    unsigned long long w0, w1;
                    asm volatile("ld.shared.v2.b64 {%0, %1}, [%2];"
                                 : "=l"(w0), "=l"(w1) : "r"(a + j * 16));
                    asm("fma.rn.f32x2 %0, %1, %2, %0;"
                        : "+l"(acc0[2 * j])     : "l"(xa2), "l"(w0));
                    asm("fma.rn.f32x2 %0, %1, %2, %0;"
                        : "+l"(acc0[2 * j + 1]) : "l"(xa2), "l"(w1));
                    asm("fma.rn.f32x2 %0, %1, %2, %0;"
                        : "+l"(acc1[2 * j])     : "l"(xb2), "l"(w0));
                    asm("fma.rn.f32x2 %0, %1, %2, %0;"
                        : "+l"(acc1[2 * j + 1]) : "l"(xb2), "l"(w1));
                }
            }
            __syncwarp();
        }

        // ---- out: transpose-scatter through the same tiles, coalesced STG ----
        #pragma unroll
        for (int nb = 0; nb < 4; nb++) {
            const uint32_t bufb = stg0 + (uint32_t)(nb & 1) * STAGE_BYTES;
            #pragma unroll
            for (int j = 0; j < 4; j++) {
                uint32_t a0 = bufb + (uint32_t)lane * PITCH + j * 16u;
                uint32_t a1 = bufb + (uint32_t)(lane + 32) * PITCH + j * 16u;
                asm volatile("st.shared.v2.b64 [%0], {%1, %2};"
                             :: "r"(a0), "l"(acc0[nb * 8 + 2 * j]),
                                         "l"(acc0[nb * 8 + 2 * j + 1]));
                asm volatile("st.shared.v2.b64 [%0], {%1, %2};"
                             :: "r"(a1), "l"(acc1[nb * 8 + 2 * j]),
                                         "l"(acc1[nb * 8 + 2 * j + 1]));
            }
            __syncwarp();
            #pragma unroll
            for (int i = 0; i < 8; i++) {
                int r = i * 8 + grow;
                unsigned long long w0, w1;
                uint32_t a = bufb + (uint32_t)r * PITCH + (uint32_t)gcol * 16u;
                asm volatile("ld.shared.v2.b64 {%0, %1}, [%2];"
                             : "=l"(w0), "=l"(w1) : "r"(a));
                if (r < nrem) {
                    float* dst = out + (size_t)tokg[i] * 64 + nb * 16 + gcol * 4;
                    asm volatile("st.global.v2.b64 [%0], {%1, %2};"
                                 :: "l"(dst), "l"(w0), "l"(w1) : "memory");
                }
            }
        }
    }
}

extern "C" void kernel_launch(void* const* d_in, const int* in_sizes, int n_in,
                              void* d_out, int out_size)
{
    const float* x   = (const float*)d_in[0];
    const int*   sel = (const int*)  d_in[1];
    const float* w   = (const float*)d_in[2];
    float*       out = (float*)d_out;

    cudaFuncSetAttribute(cvmm_kernel,
                         cudaFuncAttributeMaxDynamicSharedMemorySize,
                         SMEM_TOTAL);
    cvmm_kernel<<<NCTA, NTHR, SMEM_TOTAL>>>(x, sel, w, out);
}

// round 16
// speedup vs baseline: 1.1552x; 1.1552x over previous
#include <cuda_runtime.h>
#include <cstdint>
#include <cstddef>

// out[m] = x[m] @ w[sel[m]]   M=262144, K=64, N=64, E=8, fp32
//
// R16: R14's transpose-staging, but the x-gather goes global->shared via
// cp.async.cg (zero register footprint, L1-bypass), double-buffered with
// commit/wait groups. Kills the register spills that sank R14 (254 regs).
// Out-scatter still coalesced through the same smem transpose tiles.

#define TOK_M   262144
#define NCTA    152
#define NTHR    256
#define NWARP   8
#define MAXTB   1760          // ceil(262144/152)=1725, padded

#define PITCH       80                        // tile row pitch: 64B + 16B pad
#define STAGE_ROWS  64
#define STAGE_BYTES (STAGE_ROWS * PITCH)      // 5120 per buffer

#define SMEM_W_BYTES   (8 * 64 * 64 * 4)                 // 131072
#define SMEM_STAGE_OFF SMEM_W_BYTES
#define SMEM_STAGE_BYT (NWARP * 2 * STAGE_BYTES)         // 81920
#define SMEM_IDX_OFF   (SMEM_STAGE_OFF + SMEM_STAGE_BYT) // u16[MAXTB]
#define SMEM_SEL_OFF   (SMEM_IDX_OFF + MAXTB * 2)        // u8[MAXTB]
#define SMEM_META_OFF  ((SMEM_SEL_OFF + MAXTB + 15) & ~15)
#define SMEM_TOTAL     (SMEM_META_OFF + 160)

static __device__ __forceinline__ uint32_t s2u(const void* p) {
    uint32_t a;
    asm("{ .reg .u64 t; cvta.to.shared.u64 t, %1; cvt.u32.u64 %0, t; }"
        : "=r"(a) : "l"(p));
    return a;
}

template<int N>
static __device__ __forceinline__ void cp_wait() {
    asm volatile("cp.async.wait_group %0;" :: "n"(N) : "memory");
}

__global__ void __launch_bounds__(NTHR, 1)
cvmm_kernel(const float* __restrict__ x, const int* __restrict__ sel,
            const float* __restrict__ w, float* __restrict__ out)
{
    extern __shared__ char smem[];
    float*          w_s      = (float*)smem;
    unsigned short* idx      = (unsigned short*)(smem + SMEM_IDX_OFF);
    unsigned char*  sel_s    = (unsigned char*)(smem + SMEM_SEL_OFF);
    int*            counts   = (int*)(smem + SMEM_META_OFF);
    int*            offs     = counts + 8;
    int*            cursor   = offs + 8;
    int*            chunkoff = cursor + 8;   // 9 entries

    const int tid = threadIdx.x;
    const int bid = blockIdx.x;
    const int t0 = (int)(((long long)bid       * TOK_M) / NCTA);
    const int t1 = (int)(((long long)(bid + 1) * TOK_M) / NCTA);
    const int TB = t1 - t0;

    if (tid < 8) counts[tid] = 0;

    // ---- stage all expert weights into smem (coalesced float4 copy) ----
    {
        const float4* wg = (const float4*)w;
        float4*       ws = (float4*)w_s;
        #pragma unroll
        for (int i = 0; i < (SMEM_W_BYTES / 16) / NTHR; i++)
            ws[tid + i * NTHR] = wg[tid + i * NTHR];
    }
    __syncthreads();

    // ---- histogram over experts; stage sel in smem ----
    for (int i = tid; i < TB; i += NTHR) {
        int e = sel[t0 + i] & 7;
        sel_s[i] = (unsigned char)e;
        atomicAdd(&counts[e], 1);
    }
    __syncthreads();

    // ---- exclusive scan + 64-token chunk offsets ----
    if (tid == 0) {
        int acc = 0, cacc = 0;
        #pragma unroll
        for (int e = 0; e < 8; e++) {
            offs[e]     = acc;
            cursor[e]   = acc;
            chunkoff[e] = cacc;
            int c = counts[e];
            acc  += c;
            cacc += (c + 63) >> 6;
        }
        chunkoff[8] = cacc;
    }
    __syncthreads();

    // ---- scatter token local indices into per-expert lists ----
    for (int i = tid; i < TB; i += NTHR) {
        int e = sel_s[i];
        int p = atomicAdd(&cursor[e], 1);
        idx[p] = (unsigned short)i;
    }
    __syncthreads();

    // ---- phase 2: 64-token single-expert chunks, 2 tokens per lane ----
    const int nchunks = chunkoff[8];
    const int warp = tid >> 5, lane = tid & 31;
    const uint32_t wsb  = s2u(w_s);
    const uint32_t stg0 = s2u(smem + SMEM_STAGE_OFF)
                        + (uint32_t)warp * 2 * STAGE_BYTES;
    const int grow = lane & 7;     // row within group of 8
    const int gcol = lane >> 3;    // 0..3 : 16-byte column

    for (int c = warp; c < nchunks; c += NWARP) {
        // expert owning chunk c (monotone chunkoff; highest match wins)
        int e = 0;
        #pragma unroll
        for (int q = 1; q < 8; q++)
            if (chunkoff[q] <= c) e = q;

        const int cc   = c - chunkoff[e];
        const int base = offs[e] + cc * 64;
        const int nrem = counts[e] - cc * 64;          // 1..64

        // token ids for this lane's gather/scatter rows (clamped)
        int tokg[8];
        #pragma unroll
        for (int i = 0; i < 8; i++) {
            int r  = i * 8 + grow;
            int li = base + (r < nrem ? r : nrem - 1);
            tokg[i] = t0 + (int)idx[li];
        }

        // per-lane smem dst offsets (row = i*8+grow, col = gcol)
        // src: x + tok*64 + kb*16 + gcol*4
        // issue K-slice 0 gather via cp.async
        #pragma unroll
        for (int i = 0; i < 8; i++) {
            uint32_t d = stg0 + (uint32_t)(i * 8 + grow) * PITCH
                              + (uint32_t)gcol * 16u;
            const float* s = x + (size_t)tokg[i] * 64 + gcol * 4;
            asm volatile("cp.async.cg.shared.global [%0], [%1], 16;"
                         :: "r"(d), "l"(s) : "memory");
        }
        asm volatile("cp.async.commit_group;" ::: "memory");

        unsigned long long acc0[32], acc1[32];
        #pragma unroll
        for (int j = 0; j < 32; j++) { acc0[j] = 0ull; acc1[j] = 0ull; }

        const uint32_t webase = wsb + (uint32_t)e * 16384u;

        #pragma unroll
        for (int kb = 0; kb < 4; kb++) {
            const uint32_t bufb = stg0 + (uint32_t)(kb & 1) * STAGE_BYTES;

            // issue next K-slice gather into the other buffer
            if (kb < 3) {
                const uint32_t nb = stg0 + (uint32_t)((kb + 1) & 1) * STAGE_BYTES;
                #pragma unroll
                for (int i = 0; i < 8; i++) {
                    uint32_t d = nb + (uint32_t)(i * 8 + grow) * PITCH
                                    + (uint32_t)gcol * 16u;
                    const float* s = x + (size_t)tokg[i] * 64
                                       + (kb + 1) * 16 + gcol * 4;
                    asm volatile("cp.async.cg.shared.global [%0], [%1], 16;"
                                 :: "r"(d), "l"(s) : "memory");
                }
                asm volatile("cp.async.commit_group;" ::: "memory");
                cp_wait<1>();
            } else {
                cp_wait<0>();
            }
            __syncwarp();

            // read my 2 tokens' 16-float K-slices (pitch 80 -> conflict-free)
            float xa[16], xb[16];
            #pragma unroll
            for (int j = 0; j < 4; j++) {
                uint32_t a0 = bufb + (uint32_t)lane * PITCH + j * 16u;
                uint32_t a1 = bufb + (uint32_t)(lane + 32) * PITCH + j * 16u;
                asm volatile("ld.shared.v4.b32 {%0,%1,%2,%3}, [%4];"
                             : "=f"(xa[4*j]), "=f"(xa[4*j+1]),
                               "=f"(xa[4*j+2]), "=f"(xa[4*j+3]) : "r"(a0));
                asm volatile("ld.shared.v4.b32 {%0,%1,%2,%3}, [%4];"
                             : "=f"(xb[4*j]), "=f"(xb[4*j+1]),
                               "=f"(xb[4*j+2]), "=f"(xb[4*j+3]) : "r"(a1));
            }

            const uint32_t kbase = webase + (uint32_t)kb * 4096u;
            #pragma unroll
            for (int k2 = 0; k2 < 16; k2++) {
                unsigned long long xa2, xb2;
                asm("mov.b64 %0, {%1, %1};" : "=l"(xa2) : "f"(xa[k2]));
                asm("mov.b64 %0, {%1, %1};" : "=l"(xb2) : "f"(xb[k2]));
                const uint32_t a = kbase + (uint32_t)k2 * 256u;
                #pragma unroll
                for (int j = 0; j < 16; j++) {
                    unsigned long long w0, w1;
                    asm volatile("ld.shared.v2.b64 {%0, %1}, [%2];"
                                 : "=l"(w0), "=l"(w1) : "r"(a + j * 16));
                    asm("fma.rn.f32x2 %0, %1, %2, %0;"
                        : "+l"(acc0[2 * j])     : "l"(xa2), "l"(w0));
                    asm("fma.rn.f32x2 %0, %1, %2, %0;"
                        : "+l"(acc0[2 * j + 1]) : "l"(xa2), "l"(w1));
                    asm("fma.rn.f32x2 %0, %1, %2, %0;"
                        : "+l"(acc1[2 * j])     : "l"(xb2), "l"(w0));
                    asm("fma.rn.f32x2 %0, %1, %2, %0;"
                        : "+l"(acc1[2 * j + 1]) : "l"(xb2), "l"(w1));
                }
            }
            __syncwarp();
        }

        // ---- out: transpose-scatter through the tiles, coalesced STG ----
        #pragma unroll
        for (int nb = 0; nb < 4; nb++) {
            const uint32_t bufb = stg0 + (uint32_t)(nb & 1) * STAGE_BYTES;
            #pragma unroll
            for (int j = 0; j < 4; j++) {
                uint32_t a0 = bufb + (uint32_t)lane * PITCH + j * 16u;
                uint32_t a1 = bufb + (uint32_t)(lane + 32) * PITCH + j * 16u;
                asm volatile("st.shared.v2.b64 [%0], {%1, %2};"
                             :: "r"(a0), "l"(acc0[nb * 8 + 2 * j]),
                                         "l"(acc0[nb * 8 + 2 * j + 1]));
                asm volatile("st.shared.v2.b64 [%0], {%1, %2};"
                             :: "r"(a1), "l"(acc1[nb * 8 + 2 * j]),
                                         "l"(acc1[nb * 8 + 2 * j + 1]));
            }
            __syncwarp();
            #pragma unroll
            for (int i = 0; i < 8; i++) {
                int r = i * 8 + grow;
                unsigned long long w0, w1;
                uint32_t a = bufb + (uint32_t)r * PITCH + (uint32_t)gcol * 16u;
                asm volatile("ld.shared.v2.b64 {%0, %1}, [%2];"
                             : "=l"(w0), "=l"(w1) : "r"(a));
                if (r < nrem) {
                    float* dst = out + (size_t)tokg[i] * 64 + nb * 16 + gcol * 4;
                    asm volatile("st.global.v2.b64 [%0], {%1, %2};"
                                 :: "l"(dst), "l"(w0), "l"(w1) : "memory");
                }
            }
            __syncwarp();
        }
    }
}

extern "C" void kernel_launch(void* const* d_in, const int* in_sizes, int n_in,
                              void* d_out, int out_size)
{
    const float* x   = (const float*)d_in[0];
    const int*   sel = (const int*)  d_in[1];
    const float* w   = (const float*)d_in[2];
    float*       out = (float*)d_out;

    cudaFuncSetAttribute(cvmm_kernel,
                         cudaFuncAttributeMaxDynamicSharedMemorySize,
                         SMEM_TOTAL);
    cvmm_kernel<<<NCTA, NTHR, SMEM_TOTAL>>>(x, sel, w, out);
}